// round 2
// baseline (speedup 1.0000x reference)
#include <cuda_runtime.h>
#include <cstdint>

// ---------------------------------------------------------------------------
// LayerNormDenseGeneral: out = LN(x) @ (kernel + lora_a@lora_b) + bias
// M=8192 (B*S), K=H=4096, N=F=4096, R=32
//
// compute_103 (no 'a') build => NO tcgen05. Use mma.sync tf32 (sm_80 baseline)
// with cp.async 4-stage pipeline. Operands pre-rounded to tf32 with cvt.rna.
// ---------------------------------------------------------------------------

#define H_DIM 4096
#define F_DIM 4096
#define M_DIM 8192

#define BM 256
#define BN 128
#define BK 32
#define NSTAGE 4
#define NCHUNK (H_DIM / BK)                 // 128
#define A_STAGE_BYTES (BM * BK * 4)         // 32768
#define B_STAGE_BYTES (BN * BK * 4)         // 16384
#define STAGE_BYTES (A_STAGE_BYTES + B_STAGE_BYTES)  // 49152
#define GEMM_SMEM (NSTAGE * STAGE_BYTES)    // 196608

// scratch (allocation-free: __device__ globals)
__device__ float g_Y[(size_t)M_DIM * H_DIM];   // LN(x), tf32-rounded, [M][K]
__device__ float g_WT[(size_t)F_DIM * H_DIM];  // W_eff^T, tf32-rounded, [N][K]

// ---------------------------------------------------------------------------
__device__ __forceinline__ uint32_t smem_u32(const void* p) {
    uint32_t a;
    asm("{ .reg .u64 t; cvta.to.shared.u64 t, %1; cvt.u32.u64 %0, t; }"
        : "=r"(a) : "l"(p));
    return a;
}

__device__ __forceinline__ float tf32r(float x) {
    uint32_t u;
    asm("cvt.rna.tf32.f32 %0, %1;" : "=r"(u) : "f"(x));
    return __uint_as_float(u);
}

__device__ __forceinline__ void cp16(uint32_t dst, const float* src) {
    uint64_t g = __cvta_generic_to_global((const void*)src);
    asm volatile("cp.async.cg.shared.global [%0], [%1], 16;"
                 :: "r"(dst), "l"(g) : "memory");
}

__device__ __forceinline__ uint32_t ldsu(uint32_t addr) {
    uint32_t v;
    asm volatile("ld.shared.b32 %0, [%1];" : "=r"(v) : "r"(addr));
    return v;
}

__device__ __forceinline__ void mma_tf32(float* d,
                                         uint32_t a0, uint32_t a1,
                                         uint32_t a2, uint32_t a3,
                                         uint32_t b0, uint32_t b1) {
    asm volatile(
        "mma.sync.aligned.m16n8k8.row.col.f32.tf32.tf32.f32 "
        "{%0,%1,%2,%3}, {%4,%5,%6,%7}, {%8,%9}, {%0,%1,%2,%3};"
        : "+f"(d[0]), "+f"(d[1]), "+f"(d[2]), "+f"(d[3])
        : "r"(a0), "r"(a1), "r"(a2), "r"(a3), "r"(b0), "r"(b1));
}

// ---------------------------------------------------------------------------
// Kernel 1: LayerNorm rows of x -> g_Y (tf32-rounded fp32)
// ---------------------------------------------------------------------------
__global__ __launch_bounds__(256, 1)
void ln_kernel(const float* __restrict__ x, const float* __restrict__ gamma,
               const float* __restrict__ beta) {
    __shared__ float sm[8];
    int row = blockIdx.x;
    const float4* xr = reinterpret_cast<const float4*>(x) + (size_t)row * (H_DIM / 4);
    float4 v[4];
    float s = 0.f;
#pragma unroll
    for (int i = 0; i < 4; i++) {
        v[i] = xr[threadIdx.x + i * 256];
        s += (v[i].x + v[i].y) + (v[i].z + v[i].w);
    }
#pragma unroll
    for (int o = 16; o > 0; o >>= 1) s += __shfl_xor_sync(0xffffffffu, s, o);
    if ((threadIdx.x & 31) == 0) sm[threadIdx.x >> 5] = s;
    __syncthreads();
    float tot = 0.f;
#pragma unroll
    for (int k = 0; k < 8; k++) tot += sm[k];
    float mean = tot * (1.0f / H_DIM);
    __syncthreads();

    float s2 = 0.f;
#pragma unroll
    for (int i = 0; i < 4; i++) {
        float a = v[i].x - mean, b = v[i].y - mean;
        float c = v[i].z - mean, d = v[i].w - mean;
        s2 += (a * a + b * b) + (c * c + d * d);
    }
#pragma unroll
    for (int o = 16; o > 0; o >>= 1) s2 += __shfl_xor_sync(0xffffffffu, s2, o);
    if ((threadIdx.x & 31) == 0) sm[threadIdx.x >> 5] = s2;
    __syncthreads();
    float t2 = 0.f;
#pragma unroll
    for (int k = 0; k < 8; k++) t2 += sm[k];
    float rstd = rsqrtf(t2 * (1.0f / H_DIM) + 1e-6f);

    const float4* g4 = reinterpret_cast<const float4*>(gamma);
    const float4* b4 = reinterpret_cast<const float4*>(beta);
    float4* yr = reinterpret_cast<float4*>(g_Y) + (size_t)row * (H_DIM / 4);
#pragma unroll
    for (int i = 0; i < 4; i++) {
        int idx = threadIdx.x + i * 256;
        float4 g = g4[idx], bb = b4[idx], o;
        o.x = tf32r((v[i].x - mean) * rstd * g.x + bb.x);
        o.y = tf32r((v[i].y - mean) * rstd * g.y + bb.y);
        o.z = tf32r((v[i].z - mean) * rstd * g.z + bb.z);
        o.w = tf32r((v[i].w - mean) * rstd * g.w + bb.w);
        yr[idx] = o;
    }
}

// ---------------------------------------------------------------------------
// Kernel 2: g_WT[f][h] = tf32( kernel[h][f] + sum_r lora_a[h][r]*lora_b[r][f] )
// 32x32 tile transpose so GEMM B operand is [N][K] K-major.
// ---------------------------------------------------------------------------
__global__ __launch_bounds__(256, 1)
void weff_kernel(const float* __restrict__ Wk, const float* __restrict__ La,
                 const float* __restrict__ Lb) {
    __shared__ float s_k[32][33], s_a[32][33], s_b[32][33], s_o[32][33];
    int tx = threadIdx.x, ty = threadIdx.y;
    int f0 = blockIdx.x * 32, h0 = blockIdx.y * 32;
#pragma unroll
    for (int r = ty; r < 32; r += 8) {
        s_k[r][tx] = Wk[(size_t)(h0 + r) * F_DIM + f0 + tx];
        s_b[r][tx] = Lb[(size_t)r * F_DIM + f0 + tx];
        s_a[r][tx] = La[(size_t)(h0 + r) * 32 + tx];
    }
    __syncthreads();
#pragma unroll
    for (int hh = ty; hh < 32; hh += 8) {
        float acc = s_k[hh][tx];
#pragma unroll
        for (int r = 0; r < 32; r++) acc += s_a[hh][r] * s_b[r][tx];
        s_o[hh][tx] = acc;
    }
    __syncthreads();
#pragma unroll
    for (int ff = ty; ff < 32; ff += 8) {
        g_WT[(size_t)(f0 + ff) * H_DIM + h0 + tx] = tf32r(s_o[tx][ff]);
    }
}

// ---------------------------------------------------------------------------
// Kernel 3: tf32 mma.sync GEMM. out[m][n] = sum_k Y[m][k]*WT[n][k] + bias[n]
// CTA 256x128, 8 warps in 4(M)x2(N), warp tile 64x64, BK=32, 4-stage cp.async.
// Smem layout: [row][32 floats], word k stored at k ^ ((row&7)<<2)
// -> conflict-free mma-fragment lds and 16B-aligned cp.async stores.
// ---------------------------------------------------------------------------
__global__ __launch_bounds__(256, 1)
void gemm_kernel(const float* __restrict__ bias, float* __restrict__ out) {
    extern __shared__ char smem[];
    const uint32_t sb = smem_u32(smem);
    const int tid = threadIdx.x;
    const int wid = tid >> 5, lane = tid & 31;
    const int l2 = lane >> 2, l3 = lane & 3;
    const int mwarp = (wid >> 1) * 64;
    const int nwarp = (wid & 1) * 64;
    const uint32_t swz = (uint32_t)l2 << 4;   // ((m&7)<<4) byte XOR

    const int mt = blockIdx.x & 31;           // M fast => A reuse within wave
    const int nt = blockIdx.x >> 5;
    const size_t m0 = (size_t)mt * BM, n0 = (size_t)nt * BN;
    const float* Ap = g_Y + m0 * H_DIM;
    const float* Bp = g_WT + n0 * H_DIM;

    // ---- chunk loader: global -> smem stage (swizzled) ----
    auto load_chunk = [&](int j, int stage) {
        const uint32_t st = sb + stage * STAGE_BYTES;
        const float* a = Ap + j * BK;
#pragma unroll
        for (int i = 0; i < 8; i++) {
            int g = tid + i * 256;
            int row = g >> 3, c = g & 7;
            uint32_t off = (uint32_t)row * 128 + (((uint32_t)c * 16) ^ (((uint32_t)row & 7) << 4));
            cp16(st + off, a + (size_t)row * H_DIM + c * 4);
        }
        const float* b = Bp + j * BK;
        const uint32_t stb = st + A_STAGE_BYTES;
#pragma unroll
        for (int i = 0; i < 4; i++) {
            int g = tid + i * 256;
            int row = g >> 3, c = g & 7;
            uint32_t off = (uint32_t)row * 128 + (((uint32_t)c * 16) ^ (((uint32_t)row & 7) << 4));
            cp16(stb + off, b + (size_t)row * H_DIM + c * 4);
        }
        asm volatile("cp.async.commit_group;" ::: "memory");
    };

    float acc[4][8][4];
#pragma unroll
    for (int mi = 0; mi < 4; mi++)
#pragma unroll
        for (int ni = 0; ni < 8; ni++)
#pragma unroll
            for (int q = 0; q < 4; q++) acc[mi][ni][q] = 0.f;

    load_chunk(0, 0);
    load_chunk(1, 1);
    load_chunk(2, 2);

    for (int j = 0; j < NCHUNK; j++) {
        const int stage = j & 3;
        asm volatile("cp.async.wait_group 2;" ::: "memory");
        __syncthreads();

        if (j + 3 < NCHUNK) load_chunk(j + 3, (j + 3) & 3);
        else asm volatile("cp.async.commit_group;" ::: "memory");

        const uint32_t stA = sb + stage * STAGE_BYTES;
        const uint32_t stB = stA + A_STAGE_BYTES;
#pragma unroll
        for (int ks = 0; ks < 4; ks++) {
            const uint32_t kw0 = (uint32_t)(ks * 8 + l3) * 4;        // byte offset of k
            const uint32_t kw1 = kw0 + 16;                            // k+4
            uint32_t af[4][4];
#pragma unroll
            for (int mi = 0; mi < 4; mi++) {
                uint32_t rb = stA + (uint32_t)(mwarp + l2 + mi * 16) * 128;
                af[mi][0] = ldsu(rb + (kw0 ^ swz));
                af[mi][1] = ldsu(rb + 1024 + (kw0 ^ swz));
                af[mi][2] = ldsu(rb + (kw1 ^ swz));
                af[mi][3] = ldsu(rb + 1024 + (kw1 ^ swz));
            }
            uint32_t bf0[8], bf1[8];
#pragma unroll
            for (int ni = 0; ni < 8; ni++) {
                uint32_t rb = stB + (uint32_t)(nwarp + l2 + ni * 8) * 128;
                bf0[ni] = ldsu(rb + (kw0 ^ swz));
                bf1[ni] = ldsu(rb + (kw1 ^ swz));
            }
#pragma unroll
            for (int mi = 0; mi < 4; mi++)
#pragma unroll
                for (int ni = 0; ni < 8; ni++)
                    mma_tf32(acc[mi][ni], af[mi][0], af[mi][1], af[mi][2], af[mi][3],
                             bf0[ni], bf1[ni]);
        }
    }

    // ---- epilogue: direct gmem stores, 32B-aligned float2 segments ----
    const float* bptr = bias + n0 + nwarp + 2 * l3;
#pragma unroll
    for (int ni = 0; ni < 8; ni++) {
        float b0 = __ldg(bptr + ni * 8);
        float b1 = __ldg(bptr + ni * 8 + 1);
        size_t gn = n0 + nwarp + (size_t)ni * 8 + 2 * l3;
#pragma unroll
        for (int mi = 0; mi < 4; mi++) {
            size_t gm = m0 + mwarp + (size_t)mi * 16 + l2;
            float2 v0 = make_float2(acc[mi][ni][0] + b0, acc[mi][ni][1] + b1);
            float2 v1 = make_float2(acc[mi][ni][2] + b0, acc[mi][ni][3] + b1);
            *reinterpret_cast<float2*>(out + gm * F_DIM + gn) = v0;
            *reinterpret_cast<float2*>(out + (gm + 8) * F_DIM + gn) = v1;
        }
    }
}

// ---------------------------------------------------------------------------
extern "C" void kernel_launch(void* const* d_in, const int* in_sizes, int n_in,
                              void* d_out, int out_size) {
    (void)in_sizes; (void)n_in; (void)out_size;
    const float* x       = (const float*)d_in[0];
    const float* scale   = (const float*)d_in[1];
    const float* ln_bias = (const float*)d_in[2];
    const float* kern    = (const float*)d_in[3];
    const float* la      = (const float*)d_in[4];
    const float* lb      = (const float*)d_in[5];
    const float* bias    = (const float*)d_in[6];
    float* out = (float*)d_out;

    cudaFuncSetAttribute(gemm_kernel,
                         cudaFuncAttributeMaxDynamicSharedMemorySize, GEMM_SMEM);

    ln_kernel<<<M_DIM, 256>>>(x, scale, ln_bias);
    weff_kernel<<<dim3(F_DIM / 32, H_DIM / 32), dim3(32, 8)>>>(kern, la, lb);
    gemm_kernel<<<(M_DIM / BM) * (F_DIM / BN), 256, GEMM_SMEM>>>(bias, out);
}